// round 12
// baseline (speedup 1.0000x reference)
#include <cuda_runtime.h>
#include <cuda_fp16.h>
#include <cstdint>

#define NTH 128
#define BM 64
#define BN 64
#define MAX_BH 32
#define MAX_T  32

#define KVBLK 16640          // KH 8192 + V 8192 + D2 256

#if defined(__CUDA_ARCH_FEAT_SM103_ALL) || (defined(__CUDA_ARCH_SPECIFIC__) && (__CUDA_ARCH_SPECIFIC__ == 1030))
#define TC_PATH 1
#else
#define TC_PATH 0
#endif

// static scratch (allowed: __device__ globals, no runtime alloc)
__device__ __align__(1024) uint8_t g_kv[(size_t)MAX_BH * MAX_T * KVBLK];

#define SWZ(x) ((x) ^ (((x) >> 3) & 0x70))

__device__ __forceinline__ uint32_t smem_u32(const void* p) {
    uint32_t a;
    asm("{ .reg .u64 t; cvta.to.shared.u64 t, %1; cvt.u32.u64 %0, t; }" : "=r"(a) : "l"(p));
    return a;
}
__device__ __forceinline__ float ex2f(float x) {
    float r; asm("ex2.approx.f32 %0, %1;" : "=f"(r) : "f"(x)); return r;
}
__device__ __forceinline__ uint32_t pack_h2(float a, float b) {
    uint32_t d; asm("cvt.rn.f16x2.f32 %0, %1, %2;" : "=r"(d) : "f"(b), "f"(a)); return d;
}
__device__ __forceinline__ void ldsm4(uint32_t* r, uint32_t addr) {
    asm volatile("ldmatrix.sync.aligned.m8n8.x4.shared.b16 {%0,%1,%2,%3}, [%4];"
        : "=r"(r[0]), "=r"(r[1]), "=r"(r[2]), "=r"(r[3]) : "r"(addr));
}
__device__ __forceinline__ void ldsm4t(uint32_t* r, uint32_t addr) {
    asm volatile("ldmatrix.sync.aligned.m8n8.x4.trans.shared.b16 {%0,%1,%2,%3}, [%4];"
        : "=r"(r[0]), "=r"(r[1]), "=r"(r[2]), "=r"(r[3]) : "r"(addr));
}
__device__ __forceinline__ void mma16816(float* c, const uint32_t* a, uint32_t b0, uint32_t b1) {
    asm volatile("mma.sync.aligned.m16n8k16.row.col.f32.f16.f16.f32 "
        "{%0,%1,%2,%3}, {%4,%5,%6,%7}, {%8,%9}, {%0,%1,%2,%3};"
        : "+f"(c[0]), "+f"(c[1]), "+f"(c[2]), "+f"(c[3])
        : "r"(a[0]), "r"(a[1]), "r"(a[2]), "r"(a[3]), "r"(b0), "r"(b1));
}
__device__ __forceinline__ void cpa16(uint32_t s, const void* g) {
    asm volatile("cp.async.cg.shared.global [%0], [%1], 16;" :: "r"(s), "l"(g));
}
__device__ __forceinline__ void cpa_commit() {
    asm volatile("cp.async.commit_group;" ::: "memory");
}
template <int N>
__device__ __forceinline__ void cpa_wait() {
    asm volatile("cp.async.wait_group %0;" :: "n"(N) : "memory");
}

#if TC_PATH
#define MBAR_INIT(a, n)  asm volatile("mbarrier.init.shared.b64 [%0], %1;" :: "r"(a), "r"(n) : "memory")
#define MBAR_EXPECT(a, tx) asm volatile("mbarrier.arrive.expect_tx.shared.b64 _, [%0], %1;" :: "r"(a), "r"(tx) : "memory")
__device__ __forceinline__ void bulk_g2s(uint32_t dst, const void* src, uint32_t bytes, uint32_t mbar) {
    asm volatile("cp.async.bulk.shared::cta.global.mbarrier::complete_tx::bytes [%0], [%1], %2, [%3];"
        :: "r"(dst), "l"(src), "r"(bytes), "r"(mbar) : "memory");
}
__device__ __forceinline__ void mbar_wait(uint32_t addr, uint32_t parity) {
    asm volatile(
        "{\n\t.reg .pred P;\n"
        "W%=:\n\t"
        "mbarrier.try_wait.parity.acquire.cta.shared::cta.b64 P, [%0], %1, 0x989680;\n\t"
        "@P bra.uni D%=;\n\t"
        "bra.uni W%=;\n"
        "D%=:\n\t}"
        :: "r"(addr), "r"(parity) : "memory");
}
#endif

// ---------------- preprocess: K->f16, V->f16, d2; smem-image (swizzled) layout --------
__global__ void __launch_bounds__(NTH)
prep_kernel(const float* __restrict__ Kg, const float* __restrict__ Vg,
            const float* __restrict__ deltag, int B, int L, int H)
{
    const int BH = B * H;
    const int numT = L / 64;
    const int bid = blockIdx.x;
    const int t  = bid / BH;
    const int bh = bid % BH;
    const int b = bh / H, h = bh % H;
    const int tid = threadIdx.x;

    const int stride = H * 64;
    const size_t head_off = (size_t)b * L * stride + (size_t)h * 64;
    const int r0 = t * 64;

    uint8_t* kvb = g_kv + (size_t)(bh * numT + t) * KVBLK;

    #pragma unroll
    for (int i = 0; i < 8; i++) {
        int idx = tid + NTH * i;            // 1024 float4s per 64x64 tile
        int row = idx >> 4, c4 = idx & 15;
        uint32_t off = SWZ((uint32_t)(row * 128 + c4 * 8));
        const size_t goff = head_off + (size_t)(r0 + row) * stride + c4 * 4;

        float4 k = *(const float4*)(Kg + goff);
        *(uint2*)(kvb + off) = make_uint2(pack_h2(k.x, k.y), pack_h2(k.z, k.w));

        float4 vv = *(const float4*)(Vg + goff);
        *(uint2*)(kvb + 8192 + off) = make_uint2(pack_h2(vv.x, vv.y), pack_h2(vv.z, vv.w));
    }
    const float LOG2E = 1.4426950408889634f;
    if (tid < 64)
        ((float*)(kvb + 16384))[tid] = deltag[(size_t)b * L + r0 + tid] * (0.125f * LOG2E);
}

// ---------------- main: TMA-bulk double-buffered flash attention ----------------
#define STG0 8192             // stages after Q region (QH 8KB)
#define SM_BARS (8192 + 2 * KVBLK)
#define SMEM_MAIN (8192 + 2 * KVBLK + 64 + 1024)

__global__ void __launch_bounds__(NTH, 4)
dsattn_mma(const float* __restrict__ Qg, const float* __restrict__ taug,
           float* __restrict__ Og, int B, int L, int H)
{
    extern __shared__ __align__(1024) char smraw[];
    const uint32_t raw32 = smem_u32(smraw);
    const uint32_t sb = (raw32 + 1023u) & ~1023u;
    char* sm = smraw + (sb - raw32);

    const int tid  = threadIdx.x;
    const int wid  = tid >> 5;
    const int lane = tid & 31;
    const int gid  = lane >> 2;
    const int tig  = lane & 3;

    const int numQT = L / BM;
    const int BH = B * H;
    const int qt = numQT - 1 - ((int)blockIdx.x / BH);   // LPT: big q-tiles first
    const int bh = (int)blockIdx.x % BH;
    const int b = bh / H, h = bh % H;

    const int stride = H * 64;
    const size_t head_off = (size_t)b * L * stride + (size_t)h * 64;
    const float* qbase = Qg + head_off;
    const uint8_t* kvrow = g_kv + (size_t)bh * numQT * KVBLK;

    const float LOG2E = 1.4426950408889634f;
    const float f2 = taug[b] * 0.125f * LOG2E;
    const int q0 = qt * BM;

#if TC_PATH
    // ---- barriers + stage-0 bulk prefetch ----
    if (tid == 0) {
        MBAR_INIT(sb + SM_BARS, 1);
        MBAR_INIT(sb + SM_BARS + 8, 1);
    }
    __syncthreads();
    if (tid == 0) {
        MBAR_EXPECT(sb + SM_BARS, KVBLK);
        bulk_g2s(sb + STG0, kvrow, KVBLK, sb + SM_BARS);
    }
#else
    {
        const uint8_t* src = kvrow;
        #pragma unroll
        for (int j = 0; j < 8; j++) {
            int ch = tid + j * NTH;
            cpa16(sb + STG0 + ch * 16, src + ch * 16);
        }
        if (tid < 16) cpa16(sb + STG0 + 16384 + tid * 16, src + 16384 + tid * 16);
        cpa_commit();
    }
#endif

    // ---- Q tile: scale, f16, swizzled panel in smem ----
    #pragma unroll
    for (int i = 0; i < 8; i++) {
        int idx = tid + NTH * i;
        int row = idx >> 4, c4 = idx & 15;
        float4 v = *(const float4*)(qbase + (size_t)(q0 + row) * stride + c4 * 4);
        v.x *= f2; v.y *= f2; v.z *= f2; v.w *= f2;
        uint32_t off = SWZ((uint32_t)(row * 128 + c4 * 8));
        *(uint2*)(sm + off) = make_uint2(pack_h2(v.x, v.y), pack_h2(v.z, v.w));
    }
    __syncthreads();

    // ---- Q fragments ----
    uint32_t qh[4][4];
    {
        int rowq = wid * 16 + (lane & 15);
        int csel = (lane >> 4) * 16;
        #pragma unroll
        for (int m = 0; m < 4; m++) {
            uint32_t off = SWZ((uint32_t)(rowq * 128 + m * 32 + csel));
            ldsm4(qh[m], sb + off);
        }
    }

    float o[8][4];
    #pragma unroll
    for (int j = 0; j < 8; j++)
        #pragma unroll
        for (int c = 0; c < 4; c++) o[j][c] = 0.f;
    float lsum0 = 0.f, lsum8 = 0.f;
    const int qg0 = q0 + wid * 16 + gid;

    for (int nt = 0; nt <= qt; nt++) {
        const int n0 = nt * BN;
        const uint32_t stg = sb + STG0 + (uint32_t)(nt & 1) * KVBLK;

#if TC_PATH
        __syncthreads();   // all threads done reading the buffer about to be overwritten
        if (nt + 1 <= qt && tid == 0) {
            const uint32_t bar = sb + SM_BARS + (uint32_t)((nt + 1) & 1) * 8;
            MBAR_EXPECT(bar, KVBLK);
            bulk_g2s(sb + STG0 + (uint32_t)((nt + 1) & 1) * KVBLK,
                     kvrow + (size_t)(nt + 1) * KVBLK, KVBLK, bar);
        }
        mbar_wait(sb + SM_BARS + (uint32_t)(nt & 1) * 8, (uint32_t)(nt >> 1) & 1);
#else
        if (nt + 1 <= qt) {
            const uint8_t* src = kvrow + (size_t)(nt + 1) * KVBLK;
            const uint32_t dst = sb + STG0 + (uint32_t)((nt + 1) & 1) * KVBLK;
            #pragma unroll
            for (int j = 0; j < 8; j++) {
                int ch = tid + j * NTH;
                cpa16(dst + ch * 16, src + ch * 16);
            }
            if (tid < 16) cpa16(dst + 16384 + tid * 16, src + 16384 + tid * 16);
            cpa_commit();
            cpa_wait<1>();
        } else {
            cpa_wait<0>();
        }
        __syncthreads();
#endif

        const float* D2 = (const float*)(sm + (stg - sb) + 16384);
        const bool diag = (nt == qt);
        const int rowk = ((lane >> 4) << 3) + (lane & 7);
        const int csub = ((lane >> 3) & 1);
        const int rowv = ((lane >> 3) & 1) * 8 + (lane & 7);
        const int csel = (lane >> 4);

        // ---- process 32-key halves: S-half -> softmax-half -> O += P V half ----
        #pragma unroll
        for (int h2 = 0; h2 < 2; h2++) {
            float s[4][4];
            #pragma unroll
            for (int jl = 0; jl < 4; jl++)
                #pragma unroll
                for (int c = 0; c < 4; c++) s[jl][c] = 0.f;
            #pragma unroll
            for (int m = 0; m < 4; m++) {
                #pragma unroll
                for (int j2 = 0; j2 < 2; j2++) {
                    int jj = 2 * h2 + j2;
                    uint32_t off = SWZ((uint32_t)((jj * 16 + rowk) * 128 + (m * 2 + csub) * 16));
                    uint32_t kb[4];
                    ldsm4(kb, stg + off);
                    mma16816(s[2 * j2],     qh[m], kb[0], kb[1]);
                    mma16816(s[2 * j2 + 1], qh[m], kb[2], kb[3]);
                }
            }

            uint32_t pa[2][4];
            #pragma unroll
            for (int jl = 0; jl < 4; jl++) {
                int jg = 4 * h2 + jl;
                int lc = 8 * jg + 2 * tig;
                float d0 = D2[lc], d1 = D2[lc + 1];
                float p0 = ex2f(s[jl][0] + d0);
                float p1 = ex2f(s[jl][1] + d1);
                float p2 = ex2f(s[jl][2] + d0);
                float p3 = ex2f(s[jl][3] + d1);
                if (diag) {
                    int sg = n0 + lc;
                    if (sg     > qg0)     p0 = 0.f;
                    if (sg + 1 > qg0)     p1 = 0.f;
                    if (sg     > qg0 + 8) p2 = 0.f;
                    if (sg + 1 > qg0 + 8) p3 = 0.f;
                }
                lsum0 += p0 + p1;
                lsum8 += p2 + p3;
                int ml = jl >> 1, hs = (jl & 1) * 2;
                pa[ml][hs]     = pack_h2(p0, p1);
                pa[ml][hs + 1] = pack_h2(p2, p3);
            }

            #pragma unroll
            for (int ml = 0; ml < 2; ml++) {
                int mg = 2 * h2 + ml;
                #pragma unroll
                for (int jj = 0; jj < 4; jj++) {
                    uint32_t off = SWZ((uint32_t)((mg * 16 + rowv) * 128 + (2 * jj + csel) * 16));
                    uint32_t vb[4];
                    ldsm4t(vb, stg + 8192 + off);
                    mma16816(o[2 * jj],     pa[ml], vb[0], vb[1]);
                    mma16816(o[2 * jj + 1], pa[ml], vb[2], vb[3]);
                }
            }
        }
#if !TC_PATH
        __syncthreads();   // stage buffer free before refill (fallback path)
#endif
    }

    // ---- reduce l, write O ----
    lsum0 += __shfl_xor_sync(0xffffffffu, lsum0, 1);
    lsum0 += __shfl_xor_sync(0xffffffffu, lsum0, 2);
    lsum8 += __shfl_xor_sync(0xffffffffu, lsum8, 1);
    lsum8 += __shfl_xor_sync(0xffffffffu, lsum8, 2);
    const float inv0 = 1.0f / lsum0;
    const float inv8 = 1.0f / lsum8;

    {
        float* orow0 = Og + head_off + (size_t)qg0 * stride;
        float* orow8 = orow0 + (size_t)8 * stride;
        #pragma unroll
        for (int j = 0; j < 8; j++) {
            int col = 8 * j + 2 * tig;
            *(float2*)(orow0 + col) = make_float2(o[j][0] * inv0, o[j][1] * inv0);
            *(float2*)(orow8 + col) = make_float2(o[j][2] * inv8, o[j][3] * inv8);
        }
    }
}

extern "C" void kernel_launch(void* const* d_in, const int* in_sizes, int n_in,
                              void* d_out, int out_size) {
    const float* Q     = (const float*)d_in[0];
    const float* K     = (const float*)d_in[1];
    const float* V     = (const float*)d_in[2];
    const float* tau   = (const float*)d_in[3];
    const float* delta = (const float*)d_in[4];
    float* O = (float*)d_out;

    const int B = in_sizes[3];
    const int L = in_sizes[4] / B;
    const int H = in_sizes[0] / (B * L * 64);
    const int BH = B * H;
    const int numQT = L / BM;

    static bool attr_set = false;
    if (!attr_set) {
        cudaFuncSetAttribute(dsattn_mma, cudaFuncAttributeMaxDynamicSharedMemorySize, SMEM_MAIN);
        attr_set = true;
    }

    prep_kernel<<<BH * numQT, NTH>>>(K, V, delta, B, L, H);
    dsattn_mma<<<numQT * BH, NTH, SMEM_MAIN>>>(Q, tau, O, B, L, H);
}